// round 1
// baseline (speedup 1.0000x reference)
#include <cuda_runtime.h>

#define BATCH 64
#define T 128
#define N 32
#define M 8
#define P 16
#define NT 256

// Global scratch for forward-pass results consumed by the backward smoother.
__device__ float g_muf[BATCH * T * N];
__device__ float g_mup[BATCH * T * N];
__device__ float g_Sigf[(size_t)BATCH * T * N * N];
__device__ float g_Sigp[(size_t)BATCH * T * N * N];

__global__ __launch_bounds__(NT) void kalman_kernel(
    const float* __restrict__ Y,      // (B,T,P)
    const float* __restrict__ U,      // (B,T,M)
    const float* __restrict__ A,      // (B,T,N,N)
    const float* __restrict__ Bm,     // (B,T,N,M)
    const float* __restrict__ C,      // (B,T,P,N)
    const float* __restrict__ mu0,    // (N)
    const float* __restrict__ Sigma0, // (N,N)
    float* __restrict__ out)          // (B,T,N,N+1)
{
    const int b = blockIdx.x;
    const int tid = threadIdx.x;

    __shared__ float sA[N * 33];
    __shared__ float sSig[N * 33];   // state cov (fwd) / smoothed cov (bwd)
    __shared__ float sSigp[N * 33];
    __shared__ float sAS[N * 33];    // A*Sig, IKC, D, Sn_raw (reused)
    __shared__ float sT1[N * 33];    // T1, G, W (reused)
    __shared__ float sSf[N * 33];    // raw Sig_f (fwd) / loaded Sig_f[t] (bwd)
    __shared__ float sC[P * 33];
    __shared__ float sCSp[P * 33];
    __shared__ float sX[N * 33];     // solve result (K^T fwd, J^T bwd)
    __shared__ float sAug[N * 65];   // Gauss-Jordan augmented system
    __shared__ float sB[N * M];
    __shared__ float smu[N], smup[N], smf[N], sd[N], fac[N], pivd[N];
    __shared__ float sy[P], su[M];

    // ---- init state ----
    if (tid < N) smu[tid] = mu0[tid];
    for (int idx = tid; idx < N * N; idx += NT)
        sSig[(idx >> 5) * 33 + (idx & 31)] = Sigma0[idx];
    __syncthreads();

    // ================= FORWARD FILTER =================
    for (int t = 0; t < T; t++) {
        const size_t bt = (size_t)(b * T + t);
        const float* Ab = A + bt * N * N;
        const float* Bb = Bm + bt * N * M;
        const float* Cb = C + bt * P * N;
        const float* yb = Y + bt * P;
        const float* ub = U + bt * M;

        for (int idx = tid; idx < N * N; idx += NT)
            sA[(idx >> 5) * 33 + (idx & 31)] = Ab[idx];
        for (int idx = tid; idx < N * M; idx += NT) sB[idx] = Bb[idx];
        for (int idx = tid; idx < P * N; idx += NT)
            sC[(idx >> 5) * 33 + (idx & 31)] = Cb[idx];
        if (tid < P) sy[tid] = yb[tid];
        if (tid < M) su[tid] = ub[tid];
        __syncthreads();

        // mu_p = A mu + B u ;  AS = A * Sig
        if (tid < N) {
            float s = 0.f;
            #pragma unroll
            for (int j = 0; j < N; j++) s += sA[tid * 33 + j] * smu[j];
            #pragma unroll
            for (int j = 0; j < M; j++) s += sB[tid * M + j] * su[j];
            smup[tid] = s;
            g_mup[bt * N + tid] = s;
        }
        for (int idx = tid; idx < N * N; idx += NT) {
            int r = idx >> 5, c = idx & 31;
            float s = 0.f;
            #pragma unroll
            for (int k = 0; k < N; k++) s += sA[r * 33 + k] * sSig[k * 33 + c];
            sAS[r * 33 + c] = s;
        }
        __syncthreads();

        // Sig_p = AS * A^T + Q
        for (int idx = tid; idx < N * N; idx += NT) {
            int r = idx >> 5, c = idx & 31;
            float s = (r == c) ? 0.01f : 0.0f;
            #pragma unroll
            for (int k = 0; k < N; k++) s += sAS[r * 33 + k] * sA[c * 33 + k];
            sSigp[r * 33 + c] = s;
            g_Sigp[bt * (N * N) + idx] = s;
        }
        __syncthreads();

        // CSp = C * Sig_p ;  resid = y - C mu_p
        for (int idx = tid; idx < P * N; idx += NT) {
            int r = idx >> 5, c = idx & 31;
            float s = 0.f;
            #pragma unroll
            for (int k = 0; k < N; k++) s += sC[r * 33 + k] * sSigp[k * 33 + c];
            sCSp[r * 33 + c] = s;
        }
        if (tid < P) {
            float s = sy[tid];
            #pragma unroll
            for (int k = 0; k < N; k++) s -= sC[tid * 33 + k] * smup[k];
            sd[tid] = s;
        }
        __syncthreads();

        // S = CSp * C^T + R into aug left; CSp into aug right
        for (int idx = tid; idx < P * P; idx += NT) {
            int r = idx / P, c = idx % P;
            float s = (r == c) ? 0.01f : 0.0f;
            #pragma unroll
            for (int k = 0; k < N; k++) s += sCSp[r * 33 + k] * sC[c * 33 + k];
            sAug[r * 65 + c] = s;
        }
        for (int idx = tid; idx < P * N; idx += NT) {
            int r = idx >> 5, c = idx & 31;
            sAug[r * 65 + P + c] = sCSp[r * 33 + c];
        }
        __syncthreads();

        // Gauss-Jordan (no row scaling): S X = CSp  ->  X = K^T (16x32)
        #pragma unroll 1
        for (int j = 0; j < P; j++) {
            if (tid < P) fac[tid] = sAug[tid * 65 + j];
            __syncthreads();
            float pinv = 1.0f / fac[j];
            if (tid == 0) pivd[j] = fac[j];
            for (int idx = tid; idx < P * 48; idx += NT) {
                int r = idx / 48, c = idx % 48;
                if (r != j) sAug[r * 65 + c] -= fac[r] * pinv * sAug[j * 65 + c];
            }
            __syncthreads();
        }
        for (int idx = tid; idx < P * N; idx += NT) {
            int r = idx >> 5, c = idx & 31;
            sX[r * 33 + c] = sAug[r * 65 + P + c] / pivd[r];
        }
        __syncthreads();

        // mu_f = mu_p + K r ;  IKC = I - K C
        if (tid < N) {
            float s = smup[tid];
            #pragma unroll
            for (int j = 0; j < P; j++) s += sX[j * 33 + tid] * sd[j];
            smu[tid] = s;
            g_muf[bt * N + tid] = s;
        }
        for (int idx = tid; idx < N * N; idx += NT) {
            int r = idx >> 5, c = idx & 31;
            float s = (r == c) ? 1.0f : 0.0f;
            #pragma unroll
            for (int j = 0; j < P; j++) s -= sX[j * 33 + r] * sC[j * 33 + c];
            sAS[r * 33 + c] = s;  // IKC
        }
        __syncthreads();

        // T1 = IKC * Sig_p
        for (int idx = tid; idx < N * N; idx += NT) {
            int r = idx >> 5, c = idx & 31;
            float s = 0.f;
            #pragma unroll
            for (int k = 0; k < N; k++) s += sAS[r * 33 + k] * sSigp[k * 33 + c];
            sT1[r * 33 + c] = s;
        }
        __syncthreads();

        // Sf_raw = T1 * IKC^T + 0.01 * X^T X
        for (int idx = tid; idx < N * N; idx += NT) {
            int r = idx >> 5, c = idx & 31;
            float s = 0.f;
            #pragma unroll
            for (int k = 0; k < N; k++) s += sT1[r * 33 + k] * sAS[c * 33 + k];
            float s2 = 0.f;
            #pragma unroll
            for (int j = 0; j < P; j++) s2 += sX[j * 33 + r] * sX[j * 33 + c];
            sSf[r * 33 + c] = s + 0.01f * s2;
        }
        __syncthreads();

        // symmetrize -> new state Sig, store to global
        for (int idx = tid; idx < N * N; idx += NT) {
            int r = idx >> 5, c = idx & 31;
            float v = 0.5f * (sSf[r * 33 + c] + sSf[c * 33 + r]);
            sSig[r * 33 + c] = v;
            g_Sigf[bt * (N * N) + idx] = v;
        }
        __syncthreads();
    }

    // ---- output at t = T-1 (filtered == smoothed) ----
    {
        const size_t bt = (size_t)(b * T + (T - 1));
        for (int idx = tid; idx < N * N; idx += NT) {
            int r = idx >> 5, c = idx & 31;
            out[(bt * N + r) * (N + 1) + 1 + c] = sSig[r * 33 + c];
        }
        if (tid < N) out[(bt * N + tid) * (N + 1)] = smu[tid];
        __syncthreads();
    }

    // ================= BACKWARD RTS SMOOTHER =================
    for (int t = T - 2; t >= 0; t--) {
        const size_t bt = (size_t)(b * T + t);
        const size_t bt1 = bt + 1;
        const float* Ab = A + bt * N * N;
        for (int idx = tid; idx < N * N; idx += NT) {
            int r = idx >> 5, c = idx & 31;
            sA[r * 33 + c] = Ab[idx];
            sSf[r * 33 + c] = g_Sigf[bt * (N * N) + idx];
            sSigp[r * 33 + c] = g_Sigp[bt1 * (N * N) + idx];
        }
        if (tid < N) {
            smf[tid] = g_muf[bt * N + tid];
            smup[tid] = g_mup[bt1 * N + tid];
        }
        __syncthreads();

        // G = A * Sig_f[t] ;  d = mu_s - mu_p[t+1] ;  D = Sig_s - Sig_p[t+1]
        for (int idx = tid; idx < N * N; idx += NT) {
            int r = idx >> 5, c = idx & 31;
            float s = 0.f;
            #pragma unroll
            for (int k = 0; k < N; k++) s += sA[r * 33 + k] * sSf[k * 33 + c];
            sT1[r * 33 + c] = s;  // G
            sAS[r * 33 + c] = sSig[r * 33 + c] - sSigp[r * 33 + c];  // D
        }
        if (tid < N) sd[tid] = smu[tid] - smup[tid];
        __syncthreads();

        // aug = [Sig_p[t+1] | G]
        for (int idx = tid; idx < N * N; idx += NT) {
            int r = idx >> 5, c = idx & 31;
            sAug[r * 65 + c] = sSigp[r * 33 + c];
            sAug[r * 65 + N + c] = sT1[r * 33 + c];
        }
        __syncthreads();

        // Gauss-Jordan: Sig_p[t+1] X = G  ->  X = J^T (32x32)
        #pragma unroll 1
        for (int j = 0; j < N; j++) {
            if (tid < N) fac[tid] = sAug[tid * 65 + j];
            __syncthreads();
            float pinv = 1.0f / fac[j];
            if (tid == 0) pivd[j] = fac[j];
            for (int idx = tid; idx < N * 64; idx += NT) {
                int r = idx >> 6, c = idx & 63;
                if (r != j) sAug[r * 65 + c] -= fac[r] * pinv * sAug[j * 65 + c];
            }
            __syncthreads();
        }
        for (int idx = tid; idx < N * N; idx += NT) {
            int r = idx >> 5, c = idx & 31;
            sX[r * 33 + c] = sAug[r * 65 + N + c] / pivd[r];
        }
        __syncthreads();

        // mu_n = mu_f + J d ;  W = D * X
        if (tid < N) {
            float s = smf[tid];
            #pragma unroll
            for (int j = 0; j < N; j++) s += sX[j * 33 + tid] * sd[j];
            smu[tid] = s;
        }
        for (int idx = tid; idx < N * N; idx += NT) {
            int r = idx >> 5, c = idx & 31;
            float s = 0.f;
            #pragma unroll
            for (int k = 0; k < N; k++) s += sAS[r * 33 + k] * sX[k * 33 + c];
            sT1[r * 33 + c] = s;  // W
        }
        __syncthreads();

        // Sn_raw = Sig_f + X^T W
        for (int idx = tid; idx < N * N; idx += NT) {
            int r = idx >> 5, c = idx & 31;
            float s = sSf[r * 33 + c];
            #pragma unroll
            for (int k = 0; k < N; k++) s += sX[k * 33 + r] * sT1[k * 33 + c];
            sAS[r * 33 + c] = s;
        }
        __syncthreads();

        // symmetrize -> new Sig_s, write output
        for (int idx = tid; idx < N * N; idx += NT) {
            int r = idx >> 5, c = idx & 31;
            float v = 0.5f * (sAS[r * 33 + c] + sAS[c * 33 + r]);
            sSig[r * 33 + c] = v;
            out[(bt * N + r) * (N + 1) + 1 + c] = v;
        }
        if (tid < N) out[(bt * N + tid) * (N + 1)] = smu[tid];
        __syncthreads();
    }
}

extern "C" void kernel_launch(void* const* d_in, const int* in_sizes, int n_in,
                              void* d_out, int out_size) {
    (void)in_sizes; (void)n_in; (void)out_size;
    kalman_kernel<<<BATCH, NT>>>(
        (const float*)d_in[0],  // Y
        (const float*)d_in[1],  // U
        (const float*)d_in[2],  // A
        (const float*)d_in[3],  // B_mat
        (const float*)d_in[4],  // C
        (const float*)d_in[5],  // mu0
        (const float*)d_in[6],  // Sigma0
        (float*)d_out);
}

// round 2
// speedup vs baseline: 2.3731x; 2.3731x over previous
#include <cuda_runtime.h>

#define BATCH 64
#define T 128
#define N 32
#define M 8
#define P 16
#define MA 33   // padded row stride for 32-wide matrices

// Global scratch
__device__ float g_muf[BATCH * T * N];
__device__ float g_mup[BATCH * T * N];
__device__ float g_Sigf[(size_t)BATCH * T * N * N];
__device__ float g_Sigp[(size_t)BATCH * T * N * N];
__device__ float g_J[(size_t)BATCH * (T - 1) * N * N];   // J_t^T for t=0..T-2

// =====================================================================
// Kernel 1: forward Kalman filter. One CTA (256 thr) per batch element.
// =====================================================================
__global__ __launch_bounds__(256, 1) void k_fwd(
    const float* __restrict__ Y, const float* __restrict__ U,
    const float* __restrict__ A, const float* __restrict__ Bm,
    const float* __restrict__ C, const float* __restrict__ mu0,
    const float* __restrict__ Sig0)
{
    const int b = blockIdx.x;
    const int tid = threadIdx.x;

    __shared__ float sA[2][N * MA];
    __shared__ float sC[2][P * MA];
    __shared__ float sB[2][N * M];
    __shared__ float sy[2][P];
    __shared__ float su[2][M];
    __shared__ float sSig[N * MA], sAS[N * MA], sSigp[N * MA], sTmp[N * MA];
    __shared__ float sCSp[P * MA];
    __shared__ float sS[P * 17];
    __shared__ float sX[P * MA];          // X = K^T (16 x 32)
    __shared__ float smu[N], smup[N], sd[P];

    // init state + load t=0 inputs
    if (tid < N) smu[tid] = mu0[tid];
    for (int i = tid; i < N * N; i += 256)
        sSig[(i >> 5) * MA + (i & 31)] = Sig0[i];
    {
        const size_t bt = (size_t)b * T;
        const float* Ab = A + bt * (N * N);
        const float* Cb = C + bt * (P * N);
        const float* Bb = Bm + bt * (N * M);
        for (int i = tid; i < N * N; i += 256) sA[0][(i >> 5) * MA + (i & 31)] = Ab[i];
        for (int i = tid; i < P * N; i += 256) sC[0][(i >> 5) * MA + (i & 31)] = Cb[i];
        for (int i = tid; i < N * M; i += 256) sB[0][i] = Bb[i];
        if (tid < P) sy[0][tid] = Y[bt * P + tid];
        if (tid < M) su[0][tid] = U[bt * M + tid];
    }
    __syncthreads();

    const int tr = tid >> 4, tc = tid & 15;
    const int r0 = tr * 2, c0 = tc * 2;

    for (int t = 0; t < T; t++) {
        const int cur = t & 1, nxt = cur ^ 1;
        const size_t bt = (size_t)b * T + t;
        const float* Ac = sA[cur];
        const float* Cc = sC[cur];

        // ---- R0: mu_p (tid<32) + AS = A*Sig (2x2 tiles) ----
        if (tid < N) {
            float s = 0.f;
            #pragma unroll
            for (int j = 0; j < N; j++) s += Ac[tid * MA + j] * smu[j];
            #pragma unroll
            for (int j = 0; j < M; j++) s += sB[cur][tid * M + j] * su[cur][j];
            smup[tid] = s;
            g_mup[bt * N + tid] = s;
        }
        {
            float a00 = 0, a01 = 0, a10 = 0, a11 = 0;
            #pragma unroll
            for (int k = 0; k < N; k++) {
                float x0 = Ac[r0 * MA + k], x1 = Ac[(r0 + 1) * MA + k];
                float y0 = sSig[k * MA + c0], y1 = sSig[k * MA + c0 + 1];
                a00 += x0 * y0; a01 += x0 * y1; a10 += x1 * y0; a11 += x1 * y1;
            }
            sAS[r0 * MA + c0] = a00;       sAS[r0 * MA + c0 + 1] = a01;
            sAS[(r0 + 1) * MA + c0] = a10; sAS[(r0 + 1) * MA + c0 + 1] = a11;
        }
        __syncthreads();

        // ---- R1: Sig_p = AS * A^T + Q ----
        {
            float a00 = (r0 == c0) ? 0.01f : 0.f, a01 = 0, a10 = 0;
            float a11 = (r0 == c0) ? 0.01f : 0.f;
            #pragma unroll
            for (int k = 0; k < N; k++) {
                float x0 = sAS[r0 * MA + k], x1 = sAS[(r0 + 1) * MA + k];
                float y0 = Ac[c0 * MA + k], y1 = Ac[(c0 + 1) * MA + k];
                a00 += x0 * y0; a01 += x0 * y1; a10 += x1 * y0; a11 += x1 * y1;
            }
            sSigp[r0 * MA + c0] = a00;       sSigp[r0 * MA + c0 + 1] = a01;
            sSigp[(r0 + 1) * MA + c0] = a10; sSigp[(r0 + 1) * MA + c0 + 1] = a11;
        }
        __syncthreads();

        // ---- R2: CSp = C*Sig_p (tid<128) | resid (128..143) | STG Sigp (>=144) ----
        if (tid < 128) {
            const int rr = (tid >> 4) * 2, cc = (tid & 15) * 2;
            float a00 = 0, a01 = 0, a10 = 0, a11 = 0;
            #pragma unroll
            for (int k = 0; k < N; k++) {
                float x0 = Cc[rr * MA + k], x1 = Cc[(rr + 1) * MA + k];
                float y0 = sSigp[k * MA + cc], y1 = sSigp[k * MA + cc + 1];
                a00 += x0 * y0; a01 += x0 * y1; a10 += x1 * y0; a11 += x1 * y1;
            }
            sCSp[rr * MA + cc] = a00;       sCSp[rr * MA + cc + 1] = a01;
            sCSp[(rr + 1) * MA + cc] = a10; sCSp[(rr + 1) * MA + cc + 1] = a11;
        } else if (tid < 144) {
            const int i = tid - 128;
            float s = sy[cur][i];
            #pragma unroll
            for (int k = 0; k < N; k++) s -= Cc[i * MA + k] * smup[k];
            sd[i] = s;
        } else {
            float* gp = g_Sigp + (bt << 10);
            for (int i = tid - 144; i < N * N; i += 112)
                gp[i] = sSigp[(i >> 5) * MA + (i & 31)];
        }
        __syncthreads();

        // ---- R3: S = CSp*C^T + R (tid<64, 2x2) ----
        if (tid < 64) {
            const int rr = (tid >> 3) * 2, cc = (tid & 7) * 2;
            float a00 = (rr == cc) ? 0.01f : 0.f, a01 = 0, a10 = 0;
            float a11 = (rr == cc) ? 0.01f : 0.f;
            #pragma unroll
            for (int k = 0; k < N; k++) {
                float x0 = sCSp[rr * MA + k], x1 = sCSp[(rr + 1) * MA + k];
                float y0 = Cc[cc * MA + k], y1 = Cc[(cc + 1) * MA + k];
                a00 += x0 * y0; a01 += x0 * y1; a10 += x1 * y0; a11 += x1 * y1;
            }
            sS[rr * 17 + cc] = a00;       sS[rr * 17 + cc + 1] = a01;
            sS[(rr + 1) * 17 + cc] = a10; sS[(rr + 1) * 17 + cc + 1] = a11;
        }
        __syncthreads();

        // ---- R4: warp0 solves S X = CSp (16x16 GJ in registers);
        //          warps 1-7 prefetch inputs for t+1 ----
        if (tid < 32) {
            const int c = tid;
            float Sc[P], Rc[P], piv[P];
            #pragma unroll
            for (int r = 0; r < P; r++) {
                Sc[r] = sS[r * 17 + (c & 15)];
                Rc[r] = sCSp[r * MA + c];
            }
            #pragma unroll
            for (int j = 0; j < P; j++) {
                float f[P];
                #pragma unroll
                for (int r = 0; r < P; r++) f[r] = __shfl_sync(0xffffffffu, Sc[r], j);
                float pinv = 1.0f / f[j];
                piv[j] = f[j];
                float sj = Sc[j] * pinv, rj = Rc[j] * pinv;
                #pragma unroll
                for (int r = 0; r < P; r++) {
                    if (r != j) { Sc[r] -= f[r] * sj; Rc[r] -= f[r] * rj; }
                }
            }
            #pragma unroll
            for (int r = 0; r < P; r++) sX[r * MA + c] = Rc[r] / piv[r];
        } else if (t + 1 < T) {
            const int pt = tid - 32;
            const size_t bt1 = bt + 1;
            const float* An = A + bt1 * (N * N);
            const float* Cn = C + bt1 * (P * N);
            const float* Bn = Bm + bt1 * (N * M);
            for (int i = pt; i < N * N; i += 224) sA[nxt][(i >> 5) * MA + (i & 31)] = An[i];
            for (int i = pt; i < P * N; i += 224) sC[nxt][(i >> 5) * MA + (i & 31)] = Cn[i];
            for (int i = pt; i < N * M; i += 224) sB[nxt][i] = Bn[i];
            if (pt < P) sy[nxt][pt] = Y[bt1 * P + pt];
            else if (pt < P + M) su[nxt][pt - P] = U[bt1 * M + (pt - P)];
        }
        __syncthreads();

        // ---- R5: mu_f (tid<32) + Sf_raw = Sigp - K*CSp (2x2, sum over j<16) ----
        if (tid < N) {
            float s = smup[tid];
            #pragma unroll
            for (int j = 0; j < P; j++) s += sX[j * MA + tid] * sd[j];
            smu[tid] = s;
            g_muf[bt * N + tid] = s;
        }
        {
            float a00 = sSigp[r0 * MA + c0],       a01 = sSigp[r0 * MA + c0 + 1];
            float a10 = sSigp[(r0 + 1) * MA + c0], a11 = sSigp[(r0 + 1) * MA + c0 + 1];
            #pragma unroll
            for (int j = 0; j < P; j++) {
                float x0 = sX[j * MA + r0], x1 = sX[j * MA + r0 + 1];
                float y0 = sCSp[j * MA + c0], y1 = sCSp[j * MA + c0 + 1];
                a00 -= x0 * y0; a01 -= x0 * y1; a10 -= x1 * y0; a11 -= x1 * y1;
            }
            sTmp[r0 * MA + c0] = a00;       sTmp[r0 * MA + c0 + 1] = a01;
            sTmp[(r0 + 1) * MA + c0] = a10; sTmp[(r0 + 1) * MA + c0 + 1] = a11;
        }
        __syncthreads();

        // ---- R6: symmetrize -> sSig, STG g_Sigf (coalesced) ----
        {
            float* gf = g_Sigf + (bt << 10);
            for (int i = tid; i < N * N; i += 256) {
                int r = i >> 5, c = i & 31;
                float v = 0.5f * (sTmp[r * MA + c] + sTmp[c * MA + r]);
                sSig[r * MA + c] = v;
                gf[i] = v;
            }
        }
        __syncthreads();
    }
}

// =====================================================================
// Kernel 2: precompute all smoother gains J_t (fully parallel over b,t).
// grid (127, 64), 128 threads. Solves Sigp_{t+1} X = A_t * Sigf_t.
// =====================================================================
__global__ __launch_bounds__(128) void k_J(const float* __restrict__ A)
{
    const int t = blockIdx.x;      // 0..T-2
    const int b = blockIdx.y;
    const size_t bt = (size_t)b * T + t;
    const int tid = threadIdx.x;

    __shared__ float sA[N * MA], sSf[N * MA], sSp[N * MA], sG[N * MA];
    __shared__ float sfac[N], spiv[N];

    const float* Ab = A + bt * (N * N);
    const float* gf = g_Sigf + (bt << 10);
    const float* gp = g_Sigp + ((bt + 1) << 10);
    for (int i = tid; i < N * N; i += 128) {
        int r = i >> 5, c = i & 31;
        sA[r * MA + c] = Ab[i];
        sSf[r * MA + c] = gf[i];
        sSp[r * MA + c] = gp[i];
    }
    __syncthreads();

    // G = A * Sf (2x2 tiles, 2 tiles per thread)
    #pragma unroll
    for (int s = 0; s < 2; s++) {
        const int id = tid + s * 128;
        const int rr = (id >> 4) * 2, cc = (id & 15) * 2;
        float a00 = 0, a01 = 0, a10 = 0, a11 = 0;
        #pragma unroll
        for (int k = 0; k < N; k++) {
            float x0 = sA[rr * MA + k], x1 = sA[(rr + 1) * MA + k];
            float y0 = sSf[k * MA + cc], y1 = sSf[k * MA + cc + 1];
            a00 += x0 * y0; a01 += x0 * y1; a10 += x1 * y0; a11 += x1 * y1;
        }
        sG[rr * MA + cc] = a00;       sG[rr * MA + cc + 1] = a01;
        sG[(rr + 1) * MA + cc] = a10; sG[(rr + 1) * MA + cc + 1] = a11;
    }
    __syncthreads();

    // Gauss-Jordan (no scaling): eliminate on [Sp | G] in place
    #pragma unroll 1
    for (int j = 0; j < N; j++) {
        if (tid < N) sfac[tid] = sSp[tid * MA + j];
        __syncthreads();
        float pinv = 1.0f / sfac[j];
        if (tid == 0) spiv[j] = sfac[j];
        for (int i = tid; i < N * 64; i += 128) {
            int r = i >> 6, c = i & 63;
            float* mat = (c < N) ? sSp : sG;
            int cc = c & 31;
            if (r != j) mat[r * MA + cc] -= sfac[r] * pinv * mat[j * MA + cc];
        }
        __syncthreads();
    }

    // X = J^T -> g_J
    float* gj = g_J + ((size_t)b * (T - 1) + t) * (N * N);
    for (int i = tid; i < N * N; i += 128) {
        int r = i >> 5, c = i & 31;
        gj[i] = sG[r * MA + c] / spiv[r];
    }
}

// =====================================================================
// Kernel 3: backward RTS recursion using precomputed J. grid=64, 256 thr.
// =====================================================================
__global__ __launch_bounds__(256, 1) void k_bwd(float* __restrict__ out)
{
    const int b = blockIdx.x;
    const int tid = threadIdx.x;

    __shared__ float sSig[N * MA], sSf[N * MA], sD[N * MA], sX[N * MA];
    __shared__ float sW[N * MA], sTmp[N * MA];
    __shared__ float smu[N], smf[N], sdl[N];

    // init at t = T-1 (smoothed == filtered)
    {
        const size_t bt = (size_t)b * T + (T - 1);
        const float* gf = g_Sigf + (bt << 10);
        for (int i = tid; i < N * N; i += 256) {
            int r = i >> 5, c = i & 31;
            float v = gf[i];
            sSig[r * MA + c] = v;
            out[(bt * N + r) * (N + 1) + 1 + c] = v;
        }
        if (tid < N) {
            float v = g_muf[bt * N + tid];
            smu[tid] = v;
            out[(bt * N + tid) * (N + 1)] = v;
        }
    }
    __syncthreads();

    const int tr = tid >> 4, tc = tid & 15;
    const int r0 = tr * 2, c0 = tc * 2;

    for (int t = T - 2; t >= 0; t--) {
        const size_t bt = (size_t)b * T + t;

        // ---- R0: load Sf, X=J^T, D = Sig_s - Sigp(t+1); d = mu_s - mu_p(t+1) ----
        {
            const float* gf = g_Sigf + (bt << 10);
            const float* gp = g_Sigp + ((bt + 1) << 10);
            const float* gj = g_J + ((size_t)b * (T - 1) + t) * (N * N);
            for (int i = tid; i < N * N; i += 256) {
                int r = i >> 5, c = i & 31;
                sSf[r * MA + c] = gf[i];
                sX[r * MA + c] = gj[i];
                sD[r * MA + c] = sSig[r * MA + c] - gp[i];
            }
            if (tid < N) {
                smf[tid] = g_muf[bt * N + tid];
                sdl[tid] = smu[tid] - g_mup[(bt + 1) * N + tid];
            }
        }
        __syncthreads();

        // ---- R1: mu_n (tid<32) + W = D*X (2x2) ----
        if (tid < N) {
            float s = smf[tid];
            #pragma unroll
            for (int j = 0; j < N; j++) s += sX[j * MA + tid] * sdl[j];
            smu[tid] = s;
        }
        {
            float a00 = 0, a01 = 0, a10 = 0, a11 = 0;
            #pragma unroll
            for (int k = 0; k < N; k++) {
                float x0 = sD[r0 * MA + k], x1 = sD[(r0 + 1) * MA + k];
                float y0 = sX[k * MA + c0], y1 = sX[k * MA + c0 + 1];
                a00 += x0 * y0; a01 += x0 * y1; a10 += x1 * y0; a11 += x1 * y1;
            }
            sW[r0 * MA + c0] = a00;       sW[r0 * MA + c0 + 1] = a01;
            sW[(r0 + 1) * MA + c0] = a10; sW[(r0 + 1) * MA + c0 + 1] = a11;
        }
        __syncthreads();

        // ---- R2: Sn_raw = Sf + X^T * W (2x2) ----
        {
            float a00 = sSf[r0 * MA + c0],       a01 = sSf[r0 * MA + c0 + 1];
            float a10 = sSf[(r0 + 1) * MA + c0], a11 = sSf[(r0 + 1) * MA + c0 + 1];
            #pragma unroll
            for (int k = 0; k < N; k++) {
                float x0 = sX[k * MA + r0], x1 = sX[k * MA + r0 + 1];
                float y0 = sW[k * MA + c0], y1 = sW[k * MA + c0 + 1];
                a00 += x0 * y0; a01 += x0 * y1; a10 += x1 * y0; a11 += x1 * y1;
            }
            sTmp[r0 * MA + c0] = a00;       sTmp[r0 * MA + c0 + 1] = a01;
            sTmp[(r0 + 1) * MA + c0] = a10; sTmp[(r0 + 1) * MA + c0 + 1] = a11;
        }
        __syncthreads();

        // ---- R3: symmetrize -> sSig + write output (coalesced) ----
        for (int i = tid; i < N * N; i += 256) {
            int r = i >> 5, c = i & 31;
            float v = 0.5f * (sTmp[r * MA + c] + sTmp[c * MA + r]);
            sSig[r * MA + c] = v;
            out[(bt * N + r) * (N + 1) + 1 + c] = v;
        }
        if (tid < N) out[(bt * N + tid) * (N + 1)] = smu[tid];
        __syncthreads();
    }
}

extern "C" void kernel_launch(void* const* d_in, const int* in_sizes, int n_in,
                              void* d_out, int out_size) {
    (void)in_sizes; (void)n_in; (void)out_size;
    const float* Y   = (const float*)d_in[0];
    const float* U   = (const float*)d_in[1];
    const float* A   = (const float*)d_in[2];
    const float* Bm  = (const float*)d_in[3];
    const float* C   = (const float*)d_in[4];
    const float* mu0 = (const float*)d_in[5];
    const float* S0  = (const float*)d_in[6];
    float* out = (float*)d_out;

    k_fwd<<<BATCH, 256>>>(Y, U, A, Bm, C, mu0, S0);
    k_J<<<dim3(T - 1, BATCH), 128>>>(A);
    k_bwd<<<BATCH, 256>>>(out);
}

// round 3
// speedup vs baseline: 3.5427x; 1.4929x over previous
#include <cuda_runtime.h>

#define BATCH 64
#define T 128
#define N 32
#define M 8
#define P 16
#define MA 34    // padded row stride (even -> float2-aligned rows)

// Global scratch
__device__ float g_muf[BATCH * T * N];
__device__ float g_mup[BATCH * T * N];
__device__ float g_Sigf[(size_t)BATCH * T * N * N];
__device__ float g_Sigp[(size_t)BATCH * T * N * N];
__device__ float g_J[(size_t)BATCH * (T - 1) * N * N];   // J_t^T

// =====================================================================
// Kernel 1: forward Kalman filter. One CTA (256 thr) per batch element.
// =====================================================================
__global__ __launch_bounds__(256, 1) void k_fwd(
    const float* __restrict__ Y, const float* __restrict__ U,
    const float* __restrict__ A, const float* __restrict__ Bm,
    const float* __restrict__ C, const float* __restrict__ mu0,
    const float* __restrict__ Sig0)
{
    const int b = blockIdx.x;
    const int tid = threadIdx.x;

    __shared__ __align__(16) float sA[2][N * MA];
    __shared__ __align__(16) float sC[2][P * MA];
    __shared__ __align__(16) float sB[2][N * M];
    __shared__ float sy[2][P], su[2][M];
    __shared__ __align__(16) float sSig[N * MA], sAS[N * MA], sSigp[N * MA];
    __shared__ __align__(16) float sCSp[P * MA];
    __shared__ __align__(16) float sS[P * 18];
    __shared__ __align__(16) float sX[P * MA];     // X = K^T (16 x 32)
    __shared__ float smu[N], smup[N], sd[P];

    // ---- init state + t=0 inputs (float2 copies) ----
    if (tid < N) smu[tid] = mu0[tid];
    for (int i2 = tid; i2 < 512; i2 += 256) {
        int r = i2 >> 4, c2 = i2 & 15;
        *(float2*)(sSig + r * MA + 2 * c2) = ((const float2*)Sig0)[i2];
    }
    {
        const size_t bt = (size_t)b * T;
        const float2* Ab = (const float2*)(A + bt * (N * N));
        const float2* Cb = (const float2*)(C + bt * (P * N));
        const float2* Bb = (const float2*)(Bm + bt * (N * M));
        for (int i2 = tid; i2 < 512; i2 += 256) {
            int r = i2 >> 4, c2 = i2 & 15;
            *(float2*)(sA[0] + r * MA + 2 * c2) = Ab[i2];
        }
        for (int i2 = tid; i2 < 256; i2 += 256) {
            int r = i2 >> 4, c2 = i2 & 15;
            *(float2*)(sC[0] + r * MA + 2 * c2) = Cb[i2];
        }
        if (tid < 128) ((float2*)sB[0])[tid] = Bb[tid];
        if (tid < P) sy[0][tid] = Y[bt * P + tid];
        if (tid < M) su[0][tid] = U[bt * M + tid];
    }
    __syncthreads();

    const int tr = tid >> 4, tc = tid & 15;
    const int r0 = tr * 2, c0 = tc * 2;

    for (int t = 0; t < T; t++) {
        const int cur = t & 1, nxt = cur ^ 1;
        const size_t bt = (size_t)b * T + t;
        const float* Ac = sA[cur];
        const float* Cc = sC[cur];

        // ---- R0: mu_p (warp0) + AS = A*Sig ----
        if (tid < N) {
            const float2* Ar = (const float2*)(Ac + tid * MA);
            float s = 0.f;
            #pragma unroll
            for (int j = 0; j < 16; j++) {
                float2 a = Ar[j];
                s += a.x * smu[2 * j] + a.y * smu[2 * j + 1];
            }
            const float2* Br = (const float2*)(sB[cur] + tid * M);
            #pragma unroll
            for (int j = 0; j < 4; j++) {
                float2 bb = Br[j];
                s += bb.x * su[cur][2 * j] + bb.y * su[cur][2 * j + 1];
            }
            smup[tid] = s;
            g_mup[bt * N + tid] = s;
        }
        {
            const float2* Xr0 = (const float2*)(Ac + r0 * MA);
            const float2* Xr1 = (const float2*)(Ac + (r0 + 1) * MA);
            float a00 = 0, a01 = 0, a10 = 0, a11 = 0;
            #pragma unroll
            for (int k2 = 0; k2 < 16; k2++) {
                float2 x0 = Xr0[k2], x1 = Xr1[k2];
                float2 y0 = *(const float2*)(sSig + (2 * k2) * MA + c0);
                float2 y1 = *(const float2*)(sSig + (2 * k2 + 1) * MA + c0);
                a00 += x0.x * y0.x + x0.y * y1.x;  a01 += x0.x * y0.y + x0.y * y1.y;
                a10 += x1.x * y0.x + x1.y * y1.x;  a11 += x1.x * y0.y + x1.y * y1.y;
            }
            *(float2*)(sAS + r0 * MA + c0) = make_float2(a00, a01);
            *(float2*)(sAS + (r0 + 1) * MA + c0) = make_float2(a10, a11);
        }
        __syncthreads();

        // ---- R1: Sig_p = AS * A^T + Q (row-row form) ----
        {
            const float2* Xr0 = (const float2*)(sAS + r0 * MA);
            const float2* Xr1 = (const float2*)(sAS + (r0 + 1) * MA);
            const float2* Yc0 = (const float2*)(Ac + c0 * MA);
            const float2* Yc1 = (const float2*)(Ac + (c0 + 1) * MA);
            float a00 = (r0 == c0) ? 0.01f : 0.f, a01 = 0, a10 = 0;
            float a11 = (r0 == c0) ? 0.01f : 0.f;
            #pragma unroll
            for (int k2 = 0; k2 < 16; k2++) {
                float2 x0 = Xr0[k2], x1 = Xr1[k2], y0 = Yc0[k2], y1 = Yc1[k2];
                a00 += x0.x * y0.x + x0.y * y0.y;  a01 += x0.x * y1.x + x0.y * y1.y;
                a10 += x1.x * y0.x + x1.y * y0.y;  a11 += x1.x * y1.x + x1.y * y1.y;
            }
            *(float2*)(sSigp + r0 * MA + c0) = make_float2(a00, a01);
            *(float2*)(sSigp + (r0 + 1) * MA + c0) = make_float2(a10, a11);
        }
        __syncthreads();

        // ---- R2: CSp = C*Sig_p (tid<128) | resid (128..143) ----
        if (tid < 128) {
            const int rr = (tid >> 4) * 2, cc = (tid & 15) * 2;
            const float2* Xr0 = (const float2*)(Cc + rr * MA);
            const float2* Xr1 = (const float2*)(Cc + (rr + 1) * MA);
            float a00 = 0, a01 = 0, a10 = 0, a11 = 0;
            #pragma unroll
            for (int k2 = 0; k2 < 16; k2++) {
                float2 x0 = Xr0[k2], x1 = Xr1[k2];
                float2 y0 = *(const float2*)(sSigp + (2 * k2) * MA + cc);
                float2 y1 = *(const float2*)(sSigp + (2 * k2 + 1) * MA + cc);
                a00 += x0.x * y0.x + x0.y * y1.x;  a01 += x0.x * y0.y + x0.y * y1.y;
                a10 += x1.x * y0.x + x1.y * y1.x;  a11 += x1.x * y0.y + x1.y * y1.y;
            }
            *(float2*)(sCSp + rr * MA + cc) = make_float2(a00, a01);
            *(float2*)(sCSp + (rr + 1) * MA + cc) = make_float2(a10, a11);
        } else if (tid < 144) {
            const int i = tid - 128;
            const float2* Cr = (const float2*)(Cc + i * MA);
            float s = sy[cur][i];
            #pragma unroll
            for (int j = 0; j < 16; j++) {
                float2 cv = Cr[j];
                s -= cv.x * smup[2 * j] + cv.y * smup[2 * j + 1];
            }
            sd[i] = s;
        }
        __syncthreads();

        // ---- R3: S = CSp*C^T + R (tid<64) | STG Sig_p (tid>=64) ----
        if (tid < 64) {
            const int rr = (tid >> 3) * 2, cc = (tid & 7) * 2;
            const float2* Xr0 = (const float2*)(sCSp + rr * MA);
            const float2* Xr1 = (const float2*)(sCSp + (rr + 1) * MA);
            const float2* Yc0 = (const float2*)(Cc + cc * MA);
            const float2* Yc1 = (const float2*)(Cc + (cc + 1) * MA);
            float a00 = (rr == cc) ? 0.01f : 0.f, a01 = 0, a10 = 0;
            float a11 = (rr == cc) ? 0.01f : 0.f;
            #pragma unroll
            for (int k2 = 0; k2 < 16; k2++) {
                float2 x0 = Xr0[k2], x1 = Xr1[k2], y0 = Yc0[k2], y1 = Yc1[k2];
                a00 += x0.x * y0.x + x0.y * y0.y;  a01 += x0.x * y1.x + x0.y * y1.y;
                a10 += x1.x * y0.x + x1.y * y0.y;  a11 += x1.x * y1.x + x1.y * y1.y;
            }
            *(float2*)(sS + rr * 18 + cc) = make_float2(a00, a01);
            *(float2*)(sS + (rr + 1) * 18 + cc) = make_float2(a10, a11);
        } else {
            float2* gp = (float2*)(g_Sigp + (bt << 10));
            for (int i2 = tid - 64; i2 < 512; i2 += 192) {
                int r = i2 >> 4, c2 = i2 & 15;
                gp[i2] = *(const float2*)(sSigp + r * MA + 2 * c2);
            }
        }
        __syncthreads();

        // ---- R4: warp0 solves S X = CSp; warps 1-7 prefetch t+1 ----
        if (tid < 32) {
            const int c = tid;
            float Sc[P], Rc[P], piv[P];
            #pragma unroll
            for (int r = 0; r < P; r++) {
                Sc[r] = sS[r * 18 + (c & 15)];
                Rc[r] = sCSp[r * MA + c];
            }
            #pragma unroll
            for (int j = 0; j < P; j++) {
                float f[P];
                #pragma unroll
                for (int r = 0; r < P; r++) f[r] = __shfl_sync(0xffffffffu, Sc[r], j);
                float pinv = 1.0f / f[j];
                piv[j] = f[j];
                float sj = Sc[j] * pinv, rj = Rc[j] * pinv;
                #pragma unroll
                for (int r = 0; r < P; r++) {
                    if (r != j) { Sc[r] -= f[r] * sj; Rc[r] -= f[r] * rj; }
                }
            }
            #pragma unroll
            for (int r = 0; r < P; r++) sX[r * MA + c] = Rc[r] / piv[r];
        } else if (t + 1 < T) {
            const int pt = tid - 32;
            const size_t bt1 = bt + 1;
            const float2* An = (const float2*)(A + bt1 * (N * N));
            const float2* Cn = (const float2*)(C + bt1 * (P * N));
            const float2* Bn = (const float2*)(Bm + bt1 * (N * M));
            for (int i2 = pt; i2 < 512; i2 += 224) {
                int r = i2 >> 4, c2 = i2 & 15;
                *(float2*)(sA[nxt] + r * MA + 2 * c2) = An[i2];
            }
            for (int i2 = pt; i2 < 256; i2 += 224) {
                int r = i2 >> 4, c2 = i2 & 15;
                *(float2*)(sC[nxt] + r * MA + 2 * c2) = Cn[i2];
            }
            if (pt < 128) ((float2*)sB[nxt])[pt] = Bn[pt];
            if (pt < P) sy[nxt][pt] = Y[bt1 * P + pt];
            else if (pt < P + M) su[nxt][pt - P] = U[bt1 * M + (pt - P)];
        }
        __syncthreads();

        // ---- R5: mu_f (warp0) + Sf = Sigp - 0.5*(X^T Z + Z^T X), fused sym ----
        if (tid < N) {
            float s = smup[tid];
            #pragma unroll
            for (int j = 0; j < P; j++) s += sX[j * MA + tid] * sd[j];
            smu[tid] = s;
            g_muf[bt * N + tid] = s;
        }
        {
            float2 p0 = *(const float2*)(sSigp + r0 * MA + c0);
            float2 p1 = *(const float2*)(sSigp + (r0 + 1) * MA + c0);
            float m00 = 0, m01 = 0, m10 = 0, m11 = 0;
            #pragma unroll
            for (int j = 0; j < P; j++) {
                float2 xr = *(const float2*)(sX + j * MA + r0);
                float2 xc = *(const float2*)(sX + j * MA + c0);
                float2 zr = *(const float2*)(sCSp + j * MA + r0);
                float2 zc = *(const float2*)(sCSp + j * MA + c0);
                m00 += xr.x * zc.x + zr.x * xc.x;
                m01 += xr.x * zc.y + zr.x * xc.y;
                m10 += xr.y * zc.x + zr.y * xc.x;
                m11 += xr.y * zc.y + zr.y * xc.y;
            }
            float v00 = p0.x - 0.5f * m00, v01 = p0.y - 0.5f * m01;
            float v10 = p1.x - 0.5f * m10, v11 = p1.y - 0.5f * m11;
            *(float2*)(sSig + r0 * MA + c0) = make_float2(v00, v01);
            *(float2*)(sSig + (r0 + 1) * MA + c0) = make_float2(v10, v11);
            float* gf = g_Sigf + (bt << 10);
            *(float2*)(gf + r0 * 32 + c0) = make_float2(v00, v01);
            *(float2*)(gf + (r0 + 1) * 32 + c0) = make_float2(v10, v11);
        }
        __syncthreads();
    }
}

// =====================================================================
// Kernel 2: precompute all smoother gains J_t (parallel over b,t).
// =====================================================================
#define MAJ 33
__global__ __launch_bounds__(128) void k_J(const float* __restrict__ A)
{
    const int t = blockIdx.x;      // 0..T-2
    const int b = blockIdx.y;
    const size_t bt = (size_t)b * T + t;
    const int tid = threadIdx.x;

    __shared__ float sA[N * MAJ], sSf[N * MAJ], sSp[N * MAJ], sG[N * MAJ];
    __shared__ float sfac[N], spiv[N];

    const float* Ab = A + bt * (N * N);
    const float* gf = g_Sigf + (bt << 10);
    const float* gp = g_Sigp + ((bt + 1) << 10);
    for (int i = tid; i < N * N; i += 128) {
        int r = i >> 5, c = i & 31;
        sA[r * MAJ + c] = Ab[i];
        sSf[r * MAJ + c] = gf[i];
        sSp[r * MAJ + c] = gp[i];
    }
    __syncthreads();

    #pragma unroll
    for (int s = 0; s < 2; s++) {
        const int id = tid + s * 128;
        const int rr = (id >> 4) * 2, cc = (id & 15) * 2;
        float a00 = 0, a01 = 0, a10 = 0, a11 = 0;
        #pragma unroll
        for (int k = 0; k < N; k++) {
            float x0 = sA[rr * MAJ + k], x1 = sA[(rr + 1) * MAJ + k];
            float y0 = sSf[k * MAJ + cc], y1 = sSf[k * MAJ + cc + 1];
            a00 += x0 * y0; a01 += x0 * y1; a10 += x1 * y0; a11 += x1 * y1;
        }
        sG[rr * MAJ + cc] = a00;       sG[rr * MAJ + cc + 1] = a01;
        sG[(rr + 1) * MAJ + cc] = a10; sG[(rr + 1) * MAJ + cc + 1] = a11;
    }
    __syncthreads();

    #pragma unroll 1
    for (int j = 0; j < N; j++) {
        if (tid < N) sfac[tid] = sSp[tid * MAJ + j];
        __syncthreads();
        float pinv = 1.0f / sfac[j];
        if (tid == 0) spiv[j] = sfac[j];
        for (int i = tid; i < N * 64; i += 128) {
            int r = i >> 6, c = i & 63;
            float* mat = (c < N) ? sSp : sG;
            int cc = c & 31;
            if (r != j) mat[r * MAJ + cc] -= sfac[r] * pinv * mat[j * MAJ + cc];
        }
        __syncthreads();
    }

    float* gj = g_J + ((size_t)b * (T - 1) + t) * (N * N);
    for (int i = tid; i < N * N; i += 128) {
        int r = i >> 5, c = i & 31;
        gj[i] = sG[r * MAJ + c] / spiv[r];
    }
}

// =====================================================================
// Kernel 3: backward RTS recursion. grid=64, 256 thr, prefetched.
// =====================================================================
__global__ __launch_bounds__(256, 1) void k_bwd(float* __restrict__ out)
{
    const int b = blockIdx.x;
    const int tid = threadIdx.x;

    __shared__ __align__(16) float sSf[2][N * MA], sJ[2][N * MA], sGp[2][N * MA];
    __shared__ __align__(16) float sE[N * MA], sW[N * MA];
    __shared__ float smu[N], smf[2][N], smp[2][N];

    const int tr = tid >> 4, tc = tid & 15;
    const int r0 = tr * 2, c0 = tc * 2;

    // ---- init at t = T-1: output + E = Sigf - Sigp ----
    {
        const size_t btL = (size_t)b * T + (T - 1);
        const float2* gfL = (const float2*)(g_Sigf + (btL << 10));
        const float2* gpL = (const float2*)(g_Sigp + (btL << 10));
        for (int i2 = tid; i2 < 512; i2 += 256) {
            int r = i2 >> 4, c = (i2 & 15) * 2;
            float2 v = gfL[i2], p = gpL[i2];
            sE[r * MA + c] = v.x - p.x;
            sE[r * MA + c + 1] = v.y - p.y;
            float* o = out + (btL * N + r) * (N + 1) + 1 + c;
            o[0] = v.x; o[1] = v.y;
        }
        if (tid < N) {
            float v = g_muf[btL * N + tid];
            smu[tid] = v;
            out[(btL * N + tid) * (N + 1)] = v;
        }
        // prefetch for t = T-2 into buffer 0
        const size_t bt = btL - 1;
        const float2* gf = (const float2*)(g_Sigf + (bt << 10));
        const float2* gp = (const float2*)(g_Sigp + (bt << 10));
        const float2* gj = (const float2*)(g_J + ((size_t)b * (T - 1) + (T - 2)) * (N * N));
        for (int i2 = tid; i2 < 512; i2 += 256) {
            int r = i2 >> 4, c = (i2 & 15) * 2;
            *(float2*)(sSf[0] + r * MA + c) = gf[i2];
            *(float2*)(sGp[0] + r * MA + c) = gp[i2];
            *(float2*)(sJ[0] + r * MA + c) = gj[i2];
        }
        if (tid < N) {
            smf[0][tid] = g_muf[bt * N + tid];
            smp[0][tid] = g_mup[(bt + 1) * N + tid];
        }
    }
    __syncthreads();

    for (int t = T - 2; t >= 0; t--) {
        const int cur = (T - 2 - t) & 1, nxt = cur ^ 1;
        const size_t bt = (size_t)b * T + t;
        const float* Jc = sJ[cur];
        const bool has = (t > 0);

        // ---- R0: issue prefetch LDGs for t-1; mu update; W = E * X ----
        float2 pf_sf0, pf_sf1, pf_gp0, pf_gp1, pf_j0, pf_j1;
        float pf_mf = 0.f, pf_mp = 0.f;
        if (has) {
            const float2* gf = (const float2*)(g_Sigf + ((bt - 1) << 10));
            const float2* gp = (const float2*)(g_Sigp + ((bt - 1) << 10));
            const float2* gj = (const float2*)(g_J + ((size_t)b * (T - 1) + (t - 1)) * (N * N));
            pf_sf0 = gf[tid];  pf_sf1 = gf[tid + 256];
            pf_gp0 = gp[tid];  pf_gp1 = gp[tid + 256];
            pf_j0  = gj[tid];  pf_j1  = gj[tid + 256];
            if (tid < N) {
                pf_mf = g_muf[(bt - 1) * N + tid];
                pf_mp = g_mup[bt * N + tid];
            }
        }
        if (tid < N) {
            float s = smf[cur][tid];
            #pragma unroll
            for (int j = 0; j < N; j++)
                s += Jc[j * MA + tid] * (smu[j] - smp[cur][j]);
            __syncwarp();
            smu[tid] = s;
        }
        {
            const float2* Xr0 = (const float2*)(sE + r0 * MA);
            const float2* Xr1 = (const float2*)(sE + (r0 + 1) * MA);
            float a00 = 0, a01 = 0, a10 = 0, a11 = 0;
            #pragma unroll
            for (int k2 = 0; k2 < 16; k2++) {
                float2 x0 = Xr0[k2], x1 = Xr1[k2];
                float2 y0 = *(const float2*)(Jc + (2 * k2) * MA + c0);
                float2 y1 = *(const float2*)(Jc + (2 * k2 + 1) * MA + c0);
                a00 += x0.x * y0.x + x0.y * y1.x;  a01 += x0.x * y0.y + x0.y * y1.y;
                a10 += x1.x * y0.x + x1.y * y1.x;  a11 += x1.x * y0.y + x1.y * y1.y;
            }
            *(float2*)(sW + r0 * MA + c0) = make_float2(a00, a01);
            *(float2*)(sW + (r0 + 1) * MA + c0) = make_float2(a10, a11);
        }
        __syncthreads();

        // ---- R1: Sn = Sf + X^T W ; write out ; E' = Sn - Sigp(t) ; stash prefetch ----
        {
            float2 f0 = *(const float2*)(sSf[cur] + r0 * MA + c0);
            float2 f1 = *(const float2*)(sSf[cur] + (r0 + 1) * MA + c0);
            float a00 = f0.x, a01 = f0.y, a10 = f1.x, a11 = f1.y;
            #pragma unroll
            for (int k = 0; k < N; k++) {
                float2 xk = *(const float2*)(Jc + k * MA + r0);
                float2 wk = *(const float2*)(sW + k * MA + c0);
                a00 += xk.x * wk.x;  a01 += xk.x * wk.y;
                a10 += xk.y * wk.x;  a11 += xk.y * wk.y;
            }
            float* o = out + (bt * N + r0) * (N + 1) + 1 + c0;
            o[0] = a00; o[1] = a01;
            o[N + 1] = a10; o[N + 2] = a11;
            float2 p0 = *(const float2*)(sGp[cur] + r0 * MA + c0);
            float2 p1 = *(const float2*)(sGp[cur] + (r0 + 1) * MA + c0);
            *(float2*)(sE + r0 * MA + c0) = make_float2(a00 - p0.x, a01 - p0.y);
            *(float2*)(sE + (r0 + 1) * MA + c0) = make_float2(a10 - p1.x, a11 - p1.y);
        }
        if (tid < N) out[(bt * N + tid) * (N + 1)] = smu[tid];
        if (has) {
            int ra = tid >> 4, ca = (tid & 15) * 2;
            int rb = (tid + 256) >> 4, cb = ((tid + 256) & 15) * 2;
            *(float2*)(sSf[nxt] + ra * MA + ca) = pf_sf0;
            *(float2*)(sSf[nxt] + rb * MA + cb) = pf_sf1;
            *(float2*)(sGp[nxt] + ra * MA + ca) = pf_gp0;
            *(float2*)(sGp[nxt] + rb * MA + cb) = pf_gp1;
            *(float2*)(sJ[nxt] + ra * MA + ca) = pf_j0;
            *(float2*)(sJ[nxt] + rb * MA + cb) = pf_j1;
            if (tid < N) { smf[nxt][tid] = pf_mf; smp[nxt][tid] = pf_mp; }
        }
        __syncthreads();
    }
}

extern "C" void kernel_launch(void* const* d_in, const int* in_sizes, int n_in,
                              void* d_out, int out_size) {
    (void)in_sizes; (void)n_in; (void)out_size;
    const float* Y   = (const float*)d_in[0];
    const float* U   = (const float*)d_in[1];
    const float* A   = (const float*)d_in[2];
    const float* Bm  = (const float*)d_in[3];
    const float* C   = (const float*)d_in[4];
    const float* mu0 = (const float*)d_in[5];
    const float* S0  = (const float*)d_in[6];
    float* out = (float*)d_out;

    k_fwd<<<BATCH, 256>>>(Y, U, A, Bm, C, mu0, S0);
    k_J<<<dim3(T - 1, BATCH), 128>>>(A);
    k_bwd<<<BATCH, 256>>>(out);
}